// round 3
// baseline (speedup 1.0000x reference)
#include <cuda_runtime.h>
#include <math.h>

#define DZ 64
#define HY 112
#define WX 112
#define SLICE (HY*WX)        /* 12544 */
#define NN (DZ*SLICE)        /* 802816 */
#define NNU 802816u
#define BM_WORDS (1u<<23)    /* bitmap for key values in [0, 2^28): 32MB */
#define MAXSRC 512           /* valid src labels are <= 334 */

__device__ int                d_parent[NN];
__device__ int                d_labels[NN];
__device__ unsigned char      d_cat[NN];
__device__ int                d_fg[MAXSRC];
__device__ int                d_bg[MAXSRC];
__device__ unsigned long long d_lsum[NN];
__device__ int                d_ccnt[NN];
__device__ unsigned int       d_bitmap[BM_WORDS];
__device__ unsigned long long d_gsum;
__device__ int                d_gregs;

// ---------------------------------------------------------------- clear
__global__ void k_clear() {
    unsigned int idx = blockIdx.x * blockDim.x + threadIdx.x;
    unsigned int stride = gridDim.x * blockDim.x;
    for (unsigned int i = idx; i < BM_WORDS; i += stride) d_bitmap[i] = 0u;
    for (unsigned int i = idx; i < NN; i += stride) { d_ccnt[i] = 0; d_lsum[i] = 0ull; }
    if (idx < MAXSRC) { d_fg[idx] = 0; d_bg[idx] = 0; }
    if (idx == 0) { d_gsum = 0ull; d_gregs = 0; }
}

// ---------------------------------------------------------------- init: category + parent
__global__ void k_init(const float* __restrict__ pred, const int* __restrict__ tgt) {
    int i = blockIdx.x * blockDim.x + threadIdx.x;
    if (i >= NN) return;
    float p0 = pred[i], p1 = pred[NN + i];
    int pl = (p1 > p0) ? 1 : 0;          // argmax over 2 channels (tie -> 0)
    int g  = (tgt[i] == 1) ? 1 : 0;
    d_cat[i] = (unsigned char)(pl + 2 * g);
    d_parent[i] = i;
}

// ---------------------------------------------------------------- union-find (lock-free)
__device__ __forceinline__ int uf_find(int x) {
    volatile int* p = d_parent;
    int px = p[x];
    while (px != x) { x = px; px = p[x]; }
    return x;
}

__device__ __forceinline__ void uf_union(int a, int b) {
    while (true) {
        a = uf_find(a);
        b = uf_find(b);
        if (a == b) return;
        if (a > b) { int t = a; a = b; b = t; }
        int old = atomicMin(&d_parent[b], a);
        if (old == b) return;
        b = old;
    }
}

__global__ void k_union() {
    int i = blockIdx.x * blockDim.x + threadIdx.x;
    if (i >= NN) return;
    int c = d_cat[i];
    int z = i / SLICE; int r = i - z * SLICE; int y = r / WX; int x = r - y * WX;
    // 13 lexicographically-negative offsets {dz,dy,dx,is6}
    const int off[13][4] = {
        {-1,-1,-1,0},{-1,-1, 0,0},{-1,-1, 1,0},
        {-1, 0,-1,0},{-1, 0, 0,1},{-1, 0, 1,0},
        {-1, 1,-1,0},{-1, 1, 0,0},{-1, 1, 1,0},
        { 0,-1,-1,0},{ 0,-1, 0,1},{ 0,-1, 1,0},
        { 0, 0,-1,1}
    };
    #pragma unroll
    for (int k = 0; k < 13; k++) {
        if (c == 0 && !off[k][3]) continue;        // TN: 6-connectivity only
        int nz = z + off[k][0], ny = y + off[k][1], nx = x + off[k][2];
        if (nz < 0 || ny < 0 || ny >= HY || nx < 0 || nx >= WX) continue;
        int j = i + off[k][0] * SLICE + off[k][1] * WX + off[k][2];
        if ((int)d_cat[j] == c) uf_union(i, j);
    }
}

__global__ void k_flatten() {
    int i = blockIdx.x * blockDim.x + threadIdx.x;
    if (i >= NN) return;
    d_labels[i] = uf_find(i);            // root == component min index
}

// ---------------------------------------------------------------- region graph,
// emulating the reference's int32-wraparound key semantics (JAX x64 disabled):
//   key32 = int32(Li * N + Lj) for every directed 26-neighbor pair with Li != Lj,
//   valid & countable iff 0 <= key32 < 2^28 (SENT canonicalized to 2^28),
//   dedup on the WRAPPED key value, src = key32 / N (<= 334), dst = key32 % N,
//   category looked up at voxel dst.
__global__ void k_edges() {
    int i = blockIdx.x * blockDim.x + threadIdx.x;
    if (i >= NN) return;
    int Li = __ldg(&d_labels[i]);
    unsigned int base = (unsigned int)Li * NNU;   // wraps mod 2^32 like the reference
    int z = i / SLICE; int r = i - z * SLICE; int y = r / WX; int x = r - y * WX;
    #pragma unroll
    for (int dz = -1; dz <= 1; dz++)
    #pragma unroll
    for (int dy = -1; dy <= 1; dy++)
    #pragma unroll
    for (int dx = -1; dx <= 1; dx++) {
        if (dz == 0 && dy == 0 && dx == 0) continue;
        int nz = z + dz, ny = y + dy, nx = x + dx;
        if (nz < 0 || nz >= DZ || ny < 0 || ny >= HY || nx < 0 || nx >= WX) continue;
        int j = i + dz * SLICE + dy * WX + dx;
        int Lj = __ldg(&d_labels[j]);
        if (Lj == Li) continue;
        unsigned int key = base + (unsigned int)Lj;     // int32 wraparound pattern
        if (key >= (1u << 28)) continue;                // negative or >= SENT32: dropped
        unsigned int word = key >> 5;
        unsigned int bit = 1u << (key & 31u);
        if (d_bitmap[word] & bit) continue;             // bits only ever set: safe skip
        unsigned int old = atomicOr(&d_bitmap[word], bit);
        if (old & bit) continue;                        // someone else inserted first
        int src = (int)(key / NNU);                     // 0..334
        int dst = (int)(key - (unsigned int)src * NNU); // 0..N-1
        int c2 = (int)d_cat[dst];
        if (c2 == 3)      atomicAdd(&d_fg[src], 1);
        else if (c2 == 0) atomicAdd(&d_bg[src], 1);
    }
}

// ---------------------------------------------------------------- per-voxel loss (fixed point)
__global__ void k_loss(const float* __restrict__ pred) {
    int i = blockIdx.x * blockDim.x + threadIdx.x;
    if (i >= NN) return;
    int c = d_cat[i];
    if (c != 1 && c != 2) return;                  // only FP/FN voxels
    int L = d_labels[i];
    // non-critical iff fg_cnt[L]==1 && bg_cnt[L]==1; counts are zero for L>=MAXSRC
    if (L < MAXSRC && d_fg[L] == 1 && d_bg[L] == 1) return;
    float p0 = pred[i], p1 = pred[NN + i];
    float p = 1.0f / (1.0f + expf(p0 - p1));       // softmax channel 1
    float g = (c == 2) ? 1.0f : 0.0f;              // FN => gt foreground
    float d = p - g;
    double v = (double)d * (double)d;              // in [0,1]
    unsigned long long fx = (unsigned long long)(v * 4294967296.0);   // Q32.32
    atomicAdd(&d_lsum[L], fx);
    atomicAdd(&d_ccnt[L], 1);
}

// ---------------------------------------------------------------- per-region mean -> global
__global__ void k_regions() {
    int i = blockIdx.x * blockDim.x + threadIdx.x;
    if (i >= NN) return;
    int cnt = d_ccnt[i];
    if (cnt <= 0) return;
    double mean = (double)d_lsum[i] * (1.0 / 4294967296.0) / (double)cnt;  // <= 1
    atomicAdd(&d_gsum, (unsigned long long)(mean * 1073741824.0));         // Q34.30
    atomicAdd(&d_gregs, 1);
}

__global__ void k_final(float* __restrict__ out) {
    int r = d_gregs;
    double s = (double)d_gsum * (1.0 / 1073741824.0);
    out[0] = (r > 0) ? (float)(s / (double)r) : 0.0f;
}

// ---------------------------------------------------------------- launch
extern "C" void kernel_launch(void* const* d_in, const int* in_sizes, int n_in,
                              void* d_out, int out_size) {
    const float* pred;
    const int*   tgt;
    if (in_sizes[0] == 2 * NN) {
        pred = (const float*)d_in[0];
        tgt  = (const int*)d_in[1];
    } else {
        pred = (const float*)d_in[1];
        tgt  = (const int*)d_in[0];
    }
    const int T = 256;
    const int GB = (NN + T - 1) / T;   // 3136 blocks
    k_clear  <<<4096, T>>>();
    k_init   <<<GB, T>>>(pred, tgt);
    k_union  <<<GB, T>>>();
    k_flatten<<<GB, T>>>();
    k_edges  <<<GB, T>>>();
    k_loss   <<<GB, T>>>(pred);
    k_regions<<<GB, T>>>();
    k_final  <<<1, 1>>>((float*)d_out);
}

// round 4
// speedup vs baseline: 2.2135x; 2.2135x over previous
#include <cuda_runtime.h>
#include <math.h>

#define DZ 64
#define HY 112
#define WX 112
#define SLICE (HY*WX)        /* 12544 */
#define NN (DZ*SLICE)        /* 802816 */
#define NNU 802816u
#define BM_WORDS (1u<<23)    /* bitmap for key values in [0, 2^28): 32MB */
#define MAXSRC 512           /* valid src labels are <= 334 */

__device__ int                d_parent[NN];
__device__ int                d_labels[NN];
__device__ unsigned char      d_cat[NN];
__device__ int                d_fg[MAXSRC];
__device__ int                d_bg[MAXSRC];
__device__ unsigned long long d_lsum[NN];
__device__ int                d_ccnt[NN];
__device__ unsigned int       d_bitmap[BM_WORDS];
__device__ unsigned long long d_gsum;
__device__ int                d_gregs;

// 13 lexicographically-negative offsets {dz,dy,dx,is6}
__device__ __constant__ int c_off[13][4] = {
    {-1,-1,-1,0},{-1,-1, 0,0},{-1,-1, 1,0},
    {-1, 0,-1,0},{-1, 0, 0,1},{-1, 0, 1,0},
    {-1, 1,-1,0},{-1, 1, 0,0},{-1, 1, 1,0},
    { 0,-1,-1,0},{ 0,-1, 0,1},{ 0,-1, 1,0},
    { 0, 0,-1,1}
};

// ---------------------------------------------------------------- clear
__global__ void k_clear() {
    unsigned int idx = blockIdx.x * blockDim.x + threadIdx.x;
    unsigned int stride = gridDim.x * blockDim.x;
    for (unsigned int i = idx; i < BM_WORDS; i += stride) d_bitmap[i] = 0u;
    for (unsigned int i = idx; i < NN; i += stride) { d_ccnt[i] = 0; d_lsum[i] = 0ull; }
    if (idx < MAXSRC) { d_fg[idx] = 0; d_bg[idx] = 0; }
    if (idx == 0) { d_gsum = 0ull; d_gregs = 0; }
}

// ---------------------------------------------------------------- init: category
__global__ void k_init(const float* __restrict__ pred, const int* __restrict__ tgt) {
    int i = blockIdx.x * blockDim.x + threadIdx.x;
    if (i >= NN) return;
    float p0 = pred[i], p1 = pred[NN + i];
    int pl = (p1 > p0) ? 1 : 0;          // argmax over 2 channels (tie -> 0)
    int g  = (tgt[i] == 1) ? 1 : 0;
    d_cat[i] = (unsigned char)(pl + 2 * g);
}

// ---------------------------------------------------------------- hook: hint forest
// parent[i] = min same-category neighbor among the 13 negative offsets (else i).
// Every written value is < i -> acyclic forest; component-min stays a root.
__global__ void k_hook() {
    int i = blockIdx.x * blockDim.x + threadIdx.x;
    if (i >= NN) return;
    int c = d_cat[i];
    int z = i / SLICE; int r = i - z * SLICE; int y = r / WX; int x = r - y * WX;
    int best = i;
    #pragma unroll
    for (int k = 0; k < 13; k++) {
        if (c == 0 && !c_off[k][3]) continue;      // TN: 6-connectivity only
        int nz = z + c_off[k][0], ny = y + c_off[k][1], nx = x + c_off[k][2];
        if (nz < 0 || ny < 0 || ny >= HY || nx < 0 || nx >= WX) continue;
        int j = i + c_off[k][0] * SLICE + c_off[k][1] * WX + c_off[k][2];
        if ((int)d_cat[j] == c && j < best) best = j;
    }
    d_parent[i] = best;
}

// ---------------------------------------------------------------- union-find
// Path-halving find (plain grandparent writes) + atomicMin hooking
// (Playne/Komura/ECL-CC style; root of a component = its min linear index).
__device__ __forceinline__ int uf_find(int x) {
    while (true) {
        int p = d_parent[x];
        if (p == x) return x;
        int gp = d_parent[p];
        if (gp == p) return p;
        d_parent[x] = gp;                // path halving
        x = gp;
    }
}

__device__ __forceinline__ void uf_union(int a, int b) {
    while (true) {
        a = uf_find(a);
        b = uf_find(b);
        if (a == b) return;
        if (a > b) { int t = a; a = b; b = t; }
        int old = atomicMin(&d_parent[b], a);
        if (old == b) return;
        b = old;
    }
}

__global__ void k_union() {
    int i = blockIdx.x * blockDim.x + threadIdx.x;
    if (i >= NN) return;
    int c = d_cat[i];
    int z = i / SLICE; int r = i - z * SLICE; int y = r / WX; int x = r - y * WX;
    #pragma unroll
    for (int k = 0; k < 13; k++) {
        if (c == 0 && !c_off[k][3]) continue;      // TN: 6-connectivity only
        int nz = z + c_off[k][0], ny = y + c_off[k][1], nx = x + c_off[k][2];
        if (nz < 0 || ny < 0 || ny >= HY || nx < 0 || nx >= WX) continue;
        int j = i + c_off[k][0] * SLICE + c_off[k][1] * WX + c_off[k][2];
        if ((int)d_cat[j] == c) uf_union(i, j);
    }
}

__global__ void k_flatten() {
    int i = blockIdx.x * blockDim.x + threadIdx.x;
    if (i >= NN) return;
    d_labels[i] = uf_find(i);            // root == component min index
}

// ---------------------------------------------------------------- region graph,
// emulating the reference's int32-wraparound key semantics (JAX x64 disabled):
//   key32 = int32(Li * N + Lj) for every directed 26-neighbor pair with Li != Lj,
//   valid & countable iff 0 <= key32 < 2^28 (SENT canonicalized to 2^28),
//   dedup on the WRAPPED key value, src = key32 / N (<= 334), dst = key32 % N,
//   category looked up at voxel dst.
__global__ void k_edges() {
    int i = blockIdx.x * blockDim.x + threadIdx.x;
    if (i >= NN) return;
    int Li = __ldg(&d_labels[i]);
    unsigned int base = (unsigned int)Li * NNU;   // wraps mod 2^32 like the reference
    int z = i / SLICE; int r = i - z * SLICE; int y = r / WX; int x = r - y * WX;
    #pragma unroll
    for (int dz = -1; dz <= 1; dz++)
    #pragma unroll
    for (int dy = -1; dy <= 1; dy++)
    #pragma unroll
    for (int dx = -1; dx <= 1; dx++) {
        if (dz == 0 && dy == 0 && dx == 0) continue;
        int nz = z + dz, ny = y + dy, nx = x + dx;
        if (nz < 0 || nz >= DZ || ny < 0 || ny >= HY || nx < 0 || nx >= WX) continue;
        int j = i + dz * SLICE + dy * WX + dx;
        int Lj = __ldg(&d_labels[j]);
        if (Lj == Li) continue;
        unsigned int key = base + (unsigned int)Lj;     // int32 wraparound pattern
        if (key >= (1u << 28)) continue;                // negative or >= SENT32: dropped
        unsigned int word = key >> 5;
        unsigned int bit = 1u << (key & 31u);
        if (d_bitmap[word] & bit) continue;             // bits only ever set: safe skip
        unsigned int old = atomicOr(&d_bitmap[word], bit);
        if (old & bit) continue;                        // someone else inserted first
        int src = (int)(key / NNU);                     // 0..334
        int dst = (int)(key - (unsigned int)src * NNU); // 0..N-1
        int c2 = (int)d_cat[dst];
        if (c2 == 3)      atomicAdd(&d_fg[src], 1);
        else if (c2 == 0) atomicAdd(&d_bg[src], 1);
    }
}

// ---------------------------------------------------------------- per-voxel loss (fixed point)
__global__ void k_loss(const float* __restrict__ pred) {
    int i = blockIdx.x * blockDim.x + threadIdx.x;
    if (i >= NN) return;
    int c = d_cat[i];
    if (c != 1 && c != 2) return;                  // only FP/FN voxels
    int L = d_labels[i];
    // non-critical iff fg_cnt[L]==1 && bg_cnt[L]==1; counts are zero for L>=MAXSRC
    if (L < MAXSRC && d_fg[L] == 1 && d_bg[L] == 1) return;
    float p0 = pred[i], p1 = pred[NN + i];
    float p = 1.0f / (1.0f + expf(p0 - p1));       // softmax channel 1
    float g = (c == 2) ? 1.0f : 0.0f;              // FN => gt foreground
    float d = p - g;
    double v = (double)d * (double)d;              // in [0,1]
    unsigned long long fx = (unsigned long long)(v * 4294967296.0);   // Q32.32
    atomicAdd(&d_lsum[L], fx);
    atomicAdd(&d_ccnt[L], 1);
}

// ---------------------------------------------------------------- per-region mean -> global
__global__ void k_regions() {
    int i = blockIdx.x * blockDim.x + threadIdx.x;
    if (i >= NN) return;
    int cnt = d_ccnt[i];
    if (cnt <= 0) return;
    double mean = (double)d_lsum[i] * (1.0 / 4294967296.0) / (double)cnt;  // <= 1
    atomicAdd(&d_gsum, (unsigned long long)(mean * 1073741824.0));         // Q34.30
    atomicAdd(&d_gregs, 1);
}

__global__ void k_final(float* __restrict__ out) {
    int r = d_gregs;
    double s = (double)d_gsum * (1.0 / 1073741824.0);
    out[0] = (r > 0) ? (float)(s / (double)r) : 0.0f;
}

// ---------------------------------------------------------------- launch
extern "C" void kernel_launch(void* const* d_in, const int* in_sizes, int n_in,
                              void* d_out, int out_size) {
    const float* pred;
    const int*   tgt;
    if (in_sizes[0] == 2 * NN) {
        pred = (const float*)d_in[0];
        tgt  = (const int*)d_in[1];
    } else {
        pred = (const float*)d_in[1];
        tgt  = (const int*)d_in[0];
    }
    const int T = 256;
    const int GB = (NN + T - 1) / T;   // 3136 blocks
    k_clear  <<<4096, T>>>();
    k_init   <<<GB, T>>>(pred, tgt);
    k_hook   <<<GB, T>>>();
    k_union  <<<GB, T>>>();
    k_flatten<<<GB, T>>>();
    k_edges  <<<GB, T>>>();
    k_loss   <<<GB, T>>>(pred);
    k_regions<<<GB, T>>>();
    k_final  <<<1, 1>>>((float*)d_out);
}